// round 17
// baseline (speedup 1.0000x reference)
#include <cuda_runtime.h>
#include <stdint.h>

#define NNODES   100000
#define NGRAPHS  128
#define HDIM     256

// Scratch (no allocation allowed): per-node aggregated value
__device__ float d_agg[NNODES];

// ---------------------------------------------------------------------------
// Kernel A: edge scatter-add.  agg[dst] += x[src].
// 8 edges/thread, front-batched int4 index loads, RED.E.ADD.F32 scatter.
// Fires the programmatic-launch trigger at block start so the PDL secondary
// (pool) is dispatched while this kernel is still running.
// ---------------------------------------------------------------------------
__global__ void edge_kernel(const int* __restrict__ ei,
                            const float* __restrict__ x,
                            int E) {
#if __CUDA_ARCH__ >= 900
    cudaTriggerProgrammaticLaunchCompletion();
#endif
    int t = blockIdx.x * blockDim.x + threadIdx.x;
    int i = t << 3;
    if (i + 7 < E) {
        const int4* sp = reinterpret_cast<const int4*>(ei + i);
        const int4* dp = reinterpret_cast<const int4*>(ei + E + i);
        int4 s0 = __ldg(sp);
        int4 s1 = __ldg(sp + 1);
        int4 d0 = __ldg(dp);
        int4 d1 = __ldg(dp + 1);
        float v0 = __ldg(x + s0.x);
        float v1 = __ldg(x + s0.y);
        float v2 = __ldg(x + s0.z);
        float v3 = __ldg(x + s0.w);
        float v4 = __ldg(x + s1.x);
        float v5 = __ldg(x + s1.y);
        float v6 = __ldg(x + s1.z);
        float v7 = __ldg(x + s1.w);
        atomicAdd(&d_agg[d0.x], v0);
        atomicAdd(&d_agg[d0.y], v1);
        atomicAdd(&d_agg[d0.z], v2);
        atomicAdd(&d_agg[d0.w], v3);
        atomicAdd(&d_agg[d1.x], v4);
        atomicAdd(&d_agg[d1.y], v5);
        atomicAdd(&d_agg[d1.z], v6);
        atomicAdd(&d_agg[d1.w], v7);
    } else if (i < E) {
        for (int e = i; e < E; e++)
            atomicAdd(&d_agg[ei[E + e]], __ldg(x + ei[e]));
    }
}

// ---------------------------------------------------------------------------
// Kernel B (PDL secondary): one block per graph.
// Prologue (independent of kernel A, overlapped via the trigger):
//   - weight constants P/Nn + b_l==0 flag
//   - binary search of this graph's [start,end) in the sorted batch input
// Then cudaGridDependencySynchronize() gates only the agg scan (~1.5us).
// ---------------------------------------------------------------------------
__global__ __launch_bounds__(HDIM)
void pool_kernel(const int* __restrict__ batch,
                 const float* __restrict__ W_l,
                 const float* __restrict__ b_l,
                 const float* __restrict__ W_out,
                 const float* __restrict__ b_out,
                 float* __restrict__ out,
                 int N) {
    const int g = blockIdx.x;
    const int t = threadIdx.x;
    const int wid = t >> 5, lid = t & 31;

    // ---- prologue: weight-only constants ----
    const float w  = W_l[t];
    const float b  = b_l[t];
    const float wo = W_out[t];
    const float bo = b_out[0];
    const int allz = __syncthreads_and(b == 0.0f);
    float p = (w > 0.0f) ? wo * w : 0.0f;
    float n = (w < 0.0f) ? wo * w : 0.0f;
    #pragma unroll
    for (int off = 16; off; off >>= 1) {
        p += __shfl_xor_sync(0xffffffffu, p, off);
        n += __shfl_xor_sync(0xffffffffu, n, off);
    }
    __shared__ float sp8[8], sn8[8];
    __shared__ int   bounds[2];
    if (lid == 0) { sp8[wid] = p; sn8[wid] = n; }

    // ---- prologue: graph bounds via binary search on batch (input only) ----
    if (t < 2) {
        const int target = g + t;
        int lo = 0, hi = N;
        while (lo < hi) {
            int m = (lo + hi) >> 1;
            if (__ldg(batch + m) < target) lo = m + 1; else hi = m;
        }
        bounds[t] = lo;
    }
    __syncthreads();
    float P = 0.0f, Nn = 0.0f;
    #pragma unroll
    for (int wI = 0; wI < 8; wI++) { P += sp8[wI]; Nn += sn8[wI]; }
    const int start = bounds[0];
    const int end   = bounds[1];
    const int len   = end - start;
    const float cnt = fmaxf((float)len, 1.0f);

    // ---- wait for edge kernel's atomics to be visible ----
#if __CUDA_ARCH__ >= 900
    cudaGridDependencySynchronize();
#endif

    __shared__ float red0[8], red1[8];

    if (allz) {
        // fast path: Sum_k wo_k*relu(v*w_k) == P*max(v,0) + Nn*min(v,0)
        float sp = 0.0f, sn = 0.0f;
        const int a0 = min((start + 3) & ~3, end);   // first 16B-aligned idx
        const int a1 = max(end & ~3, a0);            // end of aligned region
        if (t < 4) {                                  // head peel (<=3)
            int hh = start + t;
            if (hh < a0) {
                float v = d_agg[hh];
                sp += fmaxf(v, 0.0f);
                sn += fminf(v, 0.0f);
            }
        } else if (t < 8) {                           // tail peel (<=3)
            int ti = a1 + (t - 4);
            if (ti < end) {
                float v = d_agg[ti];
                sp += fmaxf(v, 0.0f);
                sn += fminf(v, 0.0f);
            }
        }
        if (a1 > a0) {
            const float4* va = reinterpret_cast<const float4*>(d_agg + a0);
            const int nv = (a1 - a0) >> 2;
            for (int i = t; i < nv; i += HDIM) {
                float4 v = va[i];
                sp += fmaxf(v.x, 0.0f) + fmaxf(v.y, 0.0f)
                    + fmaxf(v.z, 0.0f) + fmaxf(v.w, 0.0f);
                sn += fminf(v.x, 0.0f) + fminf(v.y, 0.0f)
                    + fminf(v.z, 0.0f) + fminf(v.w, 0.0f);
            }
        }
        #pragma unroll
        for (int off = 16; off; off >>= 1) {
            sp += __shfl_xor_sync(0xffffffffu, sp, off);
            sn += __shfl_xor_sync(0xffffffffu, sn, off);
        }
        if (lid == 0) { red0[wid] = sp; red1[wid] = sn; }
        __syncthreads();
        if (t == 0) {
            float SP = 0.0f, SN = 0.0f;
            #pragma unroll
            for (int wI = 0; wI < 8; wI++) { SP += red0[wI]; SN += red1[wI]; }
            out[g] = fmaxf((P * SP + Nn * SN) / cnt + bo, 0.0f);
        }
        return;
    }

    // exact slow path (general b_l): one thread per feature
    float acc = 0.0f;
    __shared__ float sa[HDIM];
    for (int base = start; base < end; base += HDIM) {
        int nn = min(HDIM, end - base);
        __syncthreads();
        if (t < nn) sa[t] = d_agg[base + t];
        __syncthreads();
        float q0 = 0.f, q1 = 0.f, q2 = 0.f, q3 = 0.f;
        int j = 0;
        for (; j + 3 < nn; j += 4) {
            q0 += fmaxf(fmaf(sa[j],     w, b), 0.0f);
            q1 += fmaxf(fmaf(sa[j + 1], w, b), 0.0f);
            q2 += fmaxf(fmaf(sa[j + 2], w, b), 0.0f);
            q3 += fmaxf(fmaf(sa[j + 3], w, b), 0.0f);
        }
        for (; j < nn; j++)
            q0 += fmaxf(fmaf(sa[j], w, b), 0.0f);
        acc += (q0 + q1) + (q2 + q3);
    }
    float val = acc * wo / cnt;
    #pragma unroll
    for (int off = 16; off; off >>= 1)
        val += __shfl_xor_sync(0xffffffffu, val, off);
    if (lid == 0) red0[wid] = val;
    __syncthreads();
    if (t == 0) {
        float v = 0.0f;
        #pragma unroll
        for (int wI = 0; wI < 8; wI++) v += red0[wI];
        out[g] = fmaxf(v + bo, 0.0f);
    }
}

// ---------------------------------------------------------------------------
// inputs (metadata order):
//   0: x float32[N]  1: ei int32[2E]  2: batch int32[N]
//   3: W_l f32[256]  4: b_l f32[256]  5: W_out f32[256]  6: b_out f32[1]
// out: float32 [128]
// ---------------------------------------------------------------------------
extern "C" void kernel_launch(void* const* d_in, const int* in_sizes, int n_in,
                              void* d_out, int out_size) {
    const float* x     = (const float*)d_in[0];
    const int*   ei    = (const int*)d_in[1];
    const int*   batch = (const int*)d_in[2];
    const float* W_l   = (const float*)d_in[3];
    const float* b_l   = (const float*)d_in[4];
    const float* W_out = (const float*)d_in[5];
    const float* b_out = (const float*)d_in[6];
    float*       out   = (float*)d_out;

    const int N = in_sizes[0];
    const int E = in_sizes[1] / 2;

    // zero agg via memset node
    void* aggp = nullptr;
    cudaGetSymbolAddress(&aggp, d_agg);
    cudaMemsetAsync(aggp, 0, (size_t)N * sizeof(float), 0);

    const int threads    = 256;
    const int edgeWork   = (E + 7) / 8;
    const int edgeBlocks = (edgeWork + threads - 1) / threads;

    edge_kernel<<<edgeBlocks, threads>>>(ei, x, E);

    // Pool as PDL secondary: the trigger in edge_kernel lets these blocks
    // start early; the prologue overlaps the scatter; the grid-dependency
    // sync gates the agg scan.  Fallback to a plain launch on any failure.
    cudaError_t lerr = cudaErrorUnknown;
    {
        cudaLaunchConfig_t cfg = {};
        cfg.gridDim  = dim3(NGRAPHS, 1, 1);
        cfg.blockDim = dim3(HDIM, 1, 1);
        cfg.dynamicSmemBytes = 0;
        cfg.stream = 0;
        cudaLaunchAttribute attrs[1];
        attrs[0].id = cudaLaunchAttributeProgrammaticStreamSerialization;
        attrs[0].val.programmaticStreamSerializationAllowed = 1;
        cfg.attrs = attrs;
        cfg.numAttrs = 1;
        lerr = cudaLaunchKernelEx(&cfg, pool_kernel,
                                  batch, W_l, b_l, W_out, b_out, out, N);
    }
    if (lerr != cudaSuccess) {
        (void)cudaGetLastError();   // clear sticky error, then plain launch
        pool_kernel<<<NGRAPHS, HDIM>>>(batch, W_l, b_l, W_out, b_out, out, N);
    }
}